// round 11
// baseline (speedup 1.0000x reference)
#include <cuda_runtime.h>
#include <math.h>

#define NW 4
#define DIM 16
#define NK 81            // 3^4 Pauli strings {I,Z,Y}^4
#define BMAX 131072
#define EPS 1e-5
#define MAXBLK 2048
#define TILE 64          // batch elements per qcircuit block
#define PITCH 148        // padded floats per element in smem (multiple of 4, 148%32=20)

// ---- device globals (no allocations allowed) ----
__device__ float  d_C[NK][4];              // coefficients [k][w]
__device__ float  d_partial[MAXBLK][8];    // per-block sums / sumsq
__device__ float4 d_qbuf[BMAX];            // per-element q (scratch)

// ============================================================
// Kernel 1: 81 blocks. Threads 0-15 build W redundantly (fused
// RZ*RY*RX -> 8 butterfly stages + CNOT permutes), then 4 warps
// compute C[w][k] for k = blockIdx.x (trace spread over lanes).
// ============================================================
__global__ void __launch_bounds__(128) precompute_kernel(const float* __restrict__ weights) {
    __shared__ float2 W[DIM][DIM];   // W[p][col]
    int tid = threadIdx.x;

    if (tid < DIM) {
        int j = tid;
        float2 a[DIM];
#pragma unroll
        for (int i = 0; i < DIM; i++) a[i] = make_float2(i == j ? 1.f : 0.f, 0.f);

#pragma unroll
        for (int l = 0; l < 2; l++) {
#pragma unroll
            for (int w = 0; w < NW; w++) {
                float cx, sx, cy, sy, cz, sz;
                __sincosf(weights[(l * NW + w) * 3 + 0] * 0.5f, &sx, &cx);
                __sincosf(weights[(l * NW + w) * 3 + 1] * 0.5f, &sy, &cy);
                __sincosf(weights[(l * NW + w) * 3 + 2] * 0.5f, &sz, &cz);
                // U = RZ*RY*RX; u10 = -conj(u01), u11 = conj(u00)
                float u00r = cz * cy * cx + sz * sy * sx;
                float u00i = cz * sy * sx - sz * cy * cx;
                float u01r = -cz * sy * cx - sz * cy * sx;
                float u01i = -cz * cy * sx + sz * sy * cx;
                const int st = 1 << (3 - w);
#pragma unroll
                for (int i = 0; i < DIM; i++) {
                    if (!(i & st)) {
                        float2 a0 = a[i], a1 = a[i | st];
                        float n0r = u00r * a0.x - u00i * a0.y + u01r * a1.x - u01i * a1.y;
                        float n0i = u00r * a0.y + u00i * a0.x + u01r * a1.y + u01i * a1.x;
                        float n1r = -u01r * a0.x - u01i * a0.y + u00r * a1.x + u00i * a1.y;
                        float n1i = -u01r * a0.y + u01i * a0.x + u00r * a1.y - u00i * a1.x;
                        a[i]      = make_float2(n0r, n0i);
                        a[i | st] = make_float2(n1r, n1i);
                    }
                }
            }
#pragma unroll
            for (int w = 0; w < NW; w++) {
                const int cm = 1 << (3 - w);
                const int tm = 1 << (3 - ((w + 1) & 3));
                float2 b[DIM];
#pragma unroll
                for (int i = 0; i < DIM; i++) b[i] = a[(i & cm) ? (i ^ tm) : i];
#pragma unroll
                for (int i = 0; i < DIM; i++) a[i] = b[i];
            }
        }
#pragma unroll
        for (int p = 0; p < DIM; p++) W[p][j] = a[p];
    }
    __syncthreads();

    // C[w][k] = (1/16) Re[(-i)^nY * sum_a r(a^m) * sum_p conj(W[p,a]) sgn_w(p) W[p,a^m]]
    int w = tid >> 5;
    int lane = tid & 31;
    int k = blockIdx.x;

    int kd[4];
    { int kk = k; kd[3] = kk % 3; kk /= 3; kd[2] = kk % 3; kk /= 3; kd[1] = kk % 3; kd[0] = kk / 3; }
    int m = 0, nY = 0;
#pragma unroll
    for (int v = 0; v < 4; v++) if (kd[v] == 2) { m |= 1 << (3 - v); nY++; }

    int a_ = lane >> 1;
    int p0 = (lane & 1) << 3;
    int am = a_ ^ m;
    float r = 1.f;
#pragma unroll
    for (int v = 0; v < 4; v++)
        if (kd[v] != 0) r *= 1.f - 2.f * (float)((am >> (3 - v)) & 1);

    float sr = 0.f, si = 0.f;
#pragma unroll
    for (int pp = 0; pp < 8; pp++) {
        int p = p0 + pp;
        float sgn = ((p >> (3 - w)) & 1) ? -1.f : 1.f;
        float2 wa = W[p][a_], wb = W[p][am];
        sr += sgn * (wa.x * wb.x + wa.y * wb.y);
        si += sgn * (wa.x * wb.y - wa.y * wb.x);
    }
    float Tr = r * sr, Ti = r * si;
#pragma unroll
    for (int off = 16; off; off >>= 1) {
        Tr += __shfl_xor_sync(0xffffffffu, Tr, off);
        Ti += __shfl_xor_sync(0xffffffffu, Ti, off);
    }
    if (lane == 0) {
        float re;
        switch (nY & 3) {
            case 0: re = Tr; break;
            case 1: re = Ti; break;
            case 2: re = -Tr; break;
            default: re = -Ti; break;
        }
        d_C[k][w] = re * (1.f / 16.f);
    }
}

// ============================================================
// Kernel 2: smem-staged pool + circuit eval + per-block stats.
// 256 threads, 64 elements/block, one thread per (element, wire).
// Staging uses STS.128 (conflict-free) — the R8 regression was
// 4x scalar STS with 8-way bank conflicts.
// ============================================================
__global__ void __launch_bounds__(256) qcircuit_kernel(const float* __restrict__ x, int B) {
    __shared__ __align__(16) float xs[TILE * PITCH];   // 37,888 B
    __shared__ float Csh[NK][4];
    __shared__ float redS[8][4], redQ[8][4];

    int tid = threadIdx.x;
    int lane = tid & 31, warp = tid >> 5;

    for (int i = tid; i < NK * 4; i += 256) ((float*)Csh)[i] = ((float*)d_C)[i];

    // coalesced stage: 64 elements * 144 floats, float4 in / float4 out
    int base_elem = blockIdx.x * TILE;
    int nelem = B - base_elem; if (nelem > TILE) nelem = TILE;
    {
        const float4* xg = (const float4*)(x + (size_t)base_elem * 144);
        int n4 = nelem * 36;
        for (int i = tid; i < n4; i += 256) {
            float4 v = xg[i];
            int idx = i * 4;                    // float index within tile
            int e = idx / 144;
            int off = idx - e * 144;            // multiple of 4
            *(float4*)(xs + e * PITCH + off) = v;   // single STS.128, conflict-free
        }
    }
    __syncthreads();

    int e = tid >> 2;        // local element 0..63
    int w = tid & 3;         // wire
    float q = 0.f;
    bool valid = (e < nelem);

    float c, s;
    {
        int r0 = (w >> 1) * 6, c0 = (w & 1) * 6;
        const float* xe = &xs[e * PITCH];
        float sum = 0.f;
#pragma unroll
        for (int ri = 0; ri < 6; ri++) {
            const float2* row = (const float2*)(xe + (r0 + ri) * 12 + c0);
            float2 p0 = row[0], p1 = row[1], p2 = row[2];
            sum += p0.x + p0.y + p1.x + p1.y + p2.x + p2.y;
        }
        __sincosf(sum * (1.f / 36.f), &s, &c);
    }

    // gather all 4 wires' cos/sin for this element (group of 4 lanes)
    float cA[4], sA[4];
    int gbase = lane & ~3;
#pragma unroll
    for (int v = 0; v < 4; v++) {
        cA[v] = __shfl_sync(0xffffffffu, c, gbase + v);
        sA[v] = __shfl_sync(0xffffffffu, s, gbase + v);
    }
    float g0[3] = {1.f, cA[0], -sA[0]};
    float g1[3] = {1.f, cA[1], -sA[1]};
    float g2[3] = {1.f, cA[2], -sA[2]};
    float g3[3] = {1.f, cA[3], -sA[3]};

#pragma unroll
    for (int k0 = 0; k0 < 3; k0++) {
        float a0 = g0[k0];
#pragma unroll
        for (int k1 = 0; k1 < 3; k1++) {
            float a1 = a0 * g1[k1];
#pragma unroll
            for (int k2 = 0; k2 < 3; k2++) {
                float a2 = a1 * g2[k2];
#pragma unroll
                for (int k3 = 0; k3 < 3; k3++) {
                    float a3 = a2 * g3[k3];
                    q = fmaf(Csh[((k0 * 3 + k1) * 3 + k2) * 3 + k3][w], a3, q);
                }
            }
        }
    }
    if (!valid) q = 0.f;
    else ((float*)d_qbuf)[(size_t)(base_elem + e) * 4 + w] = q;   // coalesced

    // wire-wise reduction: xor over lane bits 2..4 keeps wire fixed
    float vq = q, vqq = q * q;
#pragma unroll
    for (int off = 4; off <= 16; off <<= 1) {
        vq  += __shfl_xor_sync(0xffffffffu, vq, off);
        vqq += __shfl_xor_sync(0xffffffffu, vqq, off);
    }
    if (lane < 4) { redS[warp][lane] = vq; redQ[warp][lane] = vqq; }
    __syncthreads();
    if (tid < 8) {
        int wi = tid & 3;
        float t = 0.f;
        if (tid < 4) {
#pragma unroll
            for (int wp = 0; wp < 8; wp++) t += redS[wp][wi];
        } else {
#pragma unroll
            for (int wp = 0; wp < 8; wp++) t += redQ[wp][wi];
        }
        d_partial[blockIdx.x][tid] = t;
    }
}

// ============================================================
// Kernel 3: fused stats-reduce + normalize (deterministic).
// ============================================================
__global__ void __launch_bounds__(256) normalize_kernel(float* __restrict__ out,
                                                        const float* __restrict__ gamma,
                                                        const float* __restrict__ beta,
                                                        int B, int nparts) {
    __shared__ double sred[256];
    __shared__ float sc_sh[4], sh_sh[4];
    int tid = threadIdx.x;

    {
        int stat = tid & 7, grp = tid >> 3;   // 32 groups
        double acc = 0.0;
        for (int j = grp; j < nparts; j += 32) acc += (double)d_partial[j][stat];
        sred[tid] = acc;
    }
    __syncthreads();
#pragma unroll
    for (int off = 128; off >= 8; off >>= 1) {
        if (tid < off) sred[tid] += sred[tid + off];
        __syncthreads();
    }
    if (tid < 4) {
        double mean = sred[tid] / (double)B;
        double var  = sred[tid + 4] / (double)B - mean * mean;
        double sc = (double)gamma[tid] / sqrt(var + (double)EPS);
        double sh = (double)beta[tid] - mean * sc;
        sc_sh[tid] = (float)sc;
        sh_sh[tid] = (float)sh;
    }
    __syncthreads();

    float4 sc = make_float4(sc_sh[0], sc_sh[1], sc_sh[2], sc_sh[3]);
    float4 sh = make_float4(sh_sh[0], sh_sh[1], sh_sh[2], sh_sh[3]);

    int i = blockIdx.x * blockDim.x + tid;
    if (i < B) {
        float4 q = d_qbuf[i];
        ((float4*)out)[i] = make_float4(fmaf(q.x, sc.x, sh.x),
                                        fmaf(q.y, sc.y, sh.y),
                                        fmaf(q.z, sc.z, sh.z),
                                        fmaf(q.w, sc.w, sh.w));
    }
}

extern "C" void kernel_launch(void* const* d_in, const int* in_sizes, int n_in,
                              void* d_out, int out_size) {
    const float* x       = (const float*)d_in[0];
    const float* weights = (const float*)d_in[1];
    const float* gamma   = (const float*)d_in[2];
    const float* beta    = (const float*)d_in[3];
    int B = in_sizes[0] / 144;
    if (B > BMAX) B = BMAX;

    precompute_kernel<<<NK, 128>>>(weights);

    int qblocks = (B + TILE - 1) / TILE;           // 2048 for B=131072
    if (qblocks > MAXBLK) qblocks = MAXBLK;
    qcircuit_kernel<<<qblocks, 256>>>(x, B);

    int nblocks = (B + 255) / 256;                 // 512
    normalize_kernel<<<nblocks, 256>>>((float*)d_out, gamma, beta, B, qblocks);
}

// round 12
// speedup vs baseline: 2.1871x; 2.1871x over previous
#include <cuda_runtime.h>
#include <math.h>

#define NW 4
#define DIM 16
#define NK 81            // 3^4 Pauli strings {I,Z,Y}^4
#define BMAX 131072
#define EPS 1e-5
#define TILE 64          // batch elements per pool block
#define PITCH 148        // padded floats per element in smem
#define EPT 4            // elements per eval thread
#define EVALBLK 128      // eval grid (256 thr): 128*256*4 = 131072

// ---- device globals (no allocations allowed) ----
__device__ float4 d_C[NK];                 // coefficients [k] -> (w0,w1,w2,w3)
__device__ float  d_partial[EVALBLK][8];   // per-eval-block sums / sumsq
__device__ float  d_t[BMAX * 4];           // pooled angles
__device__ float4 d_qbuf[BMAX];            // per-element q (scratch)

// ============================================================
// Kernel 1: 81 blocks. Threads 0-15 build W redundantly (fused
// RZ*RY*RX -> 8 butterfly stages + CNOT permutes), then 4 warps
// compute C[w][k] for k = blockIdx.x (trace spread over lanes).
// ============================================================
__global__ void __launch_bounds__(128) precompute_kernel(const float* __restrict__ weights) {
    __shared__ float2 W[DIM][DIM];   // W[p][col]
    int tid = threadIdx.x;

    if (tid < DIM) {
        int j = tid;
        float2 a[DIM];
#pragma unroll
        for (int i = 0; i < DIM; i++) a[i] = make_float2(i == j ? 1.f : 0.f, 0.f);

#pragma unroll
        for (int l = 0; l < 2; l++) {
#pragma unroll
            for (int w = 0; w < NW; w++) {
                float cx, sx, cy, sy, cz, sz;
                __sincosf(weights[(l * NW + w) * 3 + 0] * 0.5f, &sx, &cx);
                __sincosf(weights[(l * NW + w) * 3 + 1] * 0.5f, &sy, &cy);
                __sincosf(weights[(l * NW + w) * 3 + 2] * 0.5f, &sz, &cz);
                // U = RZ*RY*RX; u10 = -conj(u01), u11 = conj(u00)
                float u00r = cz * cy * cx + sz * sy * sx;
                float u00i = cz * sy * sx - sz * cy * cx;
                float u01r = -cz * sy * cx - sz * cy * sx;
                float u01i = -cz * cy * sx + sz * sy * cx;
                const int st = 1 << (3 - w);
#pragma unroll
                for (int i = 0; i < DIM; i++) {
                    if (!(i & st)) {
                        float2 a0 = a[i], a1 = a[i | st];
                        float n0r = u00r * a0.x - u00i * a0.y + u01r * a1.x - u01i * a1.y;
                        float n0i = u00r * a0.y + u00i * a0.x + u01r * a1.y + u01i * a1.x;
                        float n1r = -u01r * a0.x - u01i * a0.y + u00r * a1.x + u00i * a1.y;
                        float n1i = -u01r * a0.y + u01i * a0.x + u00r * a1.y - u00i * a1.x;
                        a[i]      = make_float2(n0r, n0i);
                        a[i | st] = make_float2(n1r, n1i);
                    }
                }
            }
#pragma unroll
            for (int w = 0; w < NW; w++) {
                const int cm = 1 << (3 - w);
                const int tm = 1 << (3 - ((w + 1) & 3));
                float2 b[DIM];
#pragma unroll
                for (int i = 0; i < DIM; i++) b[i] = a[(i & cm) ? (i ^ tm) : i];
#pragma unroll
                for (int i = 0; i < DIM; i++) a[i] = b[i];
            }
        }
#pragma unroll
        for (int p = 0; p < DIM; p++) W[p][j] = a[p];
    }
    __syncthreads();

    // C[w][k] = (1/16) Re[(-i)^nY * sum_a r(a^m) * sum_p conj(W[p,a]) sgn_w(p) W[p,a^m]]
    int w = tid >> 5;
    int lane = tid & 31;
    int k = blockIdx.x;

    int kd[4];
    { int kk = k; kd[3] = kk % 3; kk /= 3; kd[2] = kk % 3; kk /= 3; kd[1] = kk % 3; kd[0] = kk / 3; }
    int m = 0, nY = 0;
#pragma unroll
    for (int v = 0; v < 4; v++) if (kd[v] == 2) { m |= 1 << (3 - v); nY++; }

    int a_ = lane >> 1;
    int p0 = (lane & 1) << 3;
    int am = a_ ^ m;
    float r = 1.f;
#pragma unroll
    for (int v = 0; v < 4; v++)
        if (kd[v] != 0) r *= 1.f - 2.f * (float)((am >> (3 - v)) & 1);

    float sr = 0.f, si = 0.f;
#pragma unroll
    for (int pp = 0; pp < 8; pp++) {
        int p = p0 + pp;
        float sgn = ((p >> (3 - w)) & 1) ? -1.f : 1.f;
        float2 wa = W[p][a_], wb = W[p][am];
        sr += sgn * (wa.x * wb.x + wa.y * wb.y);
        si += sgn * (wa.x * wb.y - wa.y * wb.x);
    }
    float Tr = r * sr, Ti = r * si;
#pragma unroll
    for (int off = 16; off; off >>= 1) {
        Tr += __shfl_xor_sync(0xffffffffu, Tr, off);
        Ti += __shfl_xor_sync(0xffffffffu, Ti, off);
    }
    if (lane == 0) {
        float re;
        switch (nY & 3) {
            case 0: re = Tr; break;
            case 1: re = Ti; break;
            case 2: re = -Tr; break;
            default: re = -Ti; break;
        }
        ((float*)d_C)[k * 4 + w] = re * (1.f / 16.f);
    }
}

// ============================================================
// Kernel 2: POOL ONLY. smem-stage 64 elements (coalesced float4
// in, STS.128), pool one 6x6 quadrant per thread, write angles.
// Pure streaming kernel: ~12us DRAM floor.
// ============================================================
__global__ void __launch_bounds__(256) pool_kernel(const float* __restrict__ x, int B) {
    __shared__ __align__(16) float xs[TILE * PITCH];   // 37,888 B
    int tid = threadIdx.x;

    int base_elem = blockIdx.x * TILE;
    int nelem = B - base_elem; if (nelem > TILE) nelem = TILE;
    {
        const float4* xg = (const float4*)(x + (size_t)base_elem * 144);
        int n4 = nelem * 36;
        for (int i = tid; i < n4; i += 256) {
            float4 v = xg[i];
            int idx = i * 4;
            int e = idx / 144;
            int off = idx - e * 144;
            *(float4*)(xs + e * PITCH + off) = v;   // STS.128, conflict-free
        }
    }
    __syncthreads();

    int e = tid >> 2;        // local element 0..63
    int w = tid & 3;         // wire
    if (e < nelem) {
        int r0 = (w >> 1) * 6, c0 = (w & 1) * 6;
        const float* xe = &xs[e * PITCH];
        float sum = 0.f;
#pragma unroll
        for (int ri = 0; ri < 6; ri++) {
            const float2* row = (const float2*)(xe + (r0 + ri) * 12 + c0);
            float2 p0 = row[0], p1 = row[1], p2 = row[2];
            sum += p0.x + p0.y + p1.x + p1.y + p2.x + p2.y;
        }
        d_t[(size_t)(base_elem + e) * 4 + w] = sum * (1.f / 36.f);  // coalesced
    }
}

// ============================================================
// Kernel 3: EVAL. Each thread handles EPT=4 elements (strided by
// total thread count -> coalesced float4 loads). Per poly term:
// ONE broadcast LDS.128 of C[k] feeds 16 FMAs. 81 LDS / 4 elems.
// ============================================================
__global__ void __launch_bounds__(256) eval_kernel(int B, int NT) {
    __shared__ float4 Csh[NK];
    __shared__ float red[8][8];
    int tid = threadIdx.x;
    int lane = tid & 31, warp = tid >> 5;
    for (int i = tid; i < NK; i += 256) Csh[i] = d_C[i];
    __syncthreads();

    int gid = blockIdx.x * 256 + tid;

    float gc[EPT][4], gs[EPT][4];
    int   eidx[EPT];
    bool  val[EPT];
#pragma unroll
    for (int j = 0; j < EPT; j++) {
        int e = gid + j * NT;
        eidx[j] = e;
        val[j] = (e < B);
        float4 tv = val[j] ? ((const float4*)d_t)[e] : make_float4(0.f, 0.f, 0.f, 0.f);
        __sincosf(tv.x, &gs[j][0], &gc[j][0]);
        __sincosf(tv.y, &gs[j][1], &gc[j][1]);
        __sincosf(tv.z, &gs[j][2], &gc[j][2]);
        __sincosf(tv.w, &gs[j][3], &gc[j][3]);
    }

    float acc[EPT][4];
#pragma unroll
    for (int j = 0; j < EPT; j++)
#pragma unroll
        for (int w = 0; w < 4; w++) acc[j][w] = 0.f;

#pragma unroll
    for (int k0 = 0; k0 < 3; k0++) {
        float a0[EPT];
#pragma unroll
        for (int j = 0; j < EPT; j++)
            a0[j] = (k0 == 0) ? 1.f : (k0 == 1) ? gc[j][0] : -gs[j][0];
#pragma unroll
        for (int k1 = 0; k1 < 3; k1++) {
            float a1[EPT];
#pragma unroll
            for (int j = 0; j < EPT; j++)
                a1[j] = (k1 == 0) ? a0[j] : (k1 == 1) ? a0[j] * gc[j][1] : -a0[j] * gs[j][1];
#pragma unroll
            for (int k2 = 0; k2 < 3; k2++) {
                float a2[EPT];
#pragma unroll
                for (int j = 0; j < EPT; j++)
                    a2[j] = (k2 == 0) ? a1[j] : (k2 == 1) ? a1[j] * gc[j][2] : -a1[j] * gs[j][2];
#pragma unroll
                for (int k3 = 0; k3 < 3; k3++) {
                    float4 cc = Csh[((k0 * 3 + k1) * 3 + k2) * 3 + k3];
#pragma unroll
                    for (int j = 0; j < EPT; j++) {
                        float a3 = (k3 == 0) ? a2[j] : (k3 == 1) ? a2[j] * gc[j][3] : -a2[j] * gs[j][3];
                        acc[j][0] = fmaf(cc.x, a3, acc[j][0]);
                        acc[j][1] = fmaf(cc.y, a3, acc[j][1]);
                        acc[j][2] = fmaf(cc.z, a3, acc[j][2]);
                        acc[j][3] = fmaf(cc.w, a3, acc[j][3]);
                    }
                }
            }
        }
    }

    float v[8] = {0.f, 0.f, 0.f, 0.f, 0.f, 0.f, 0.f, 0.f};
#pragma unroll
    for (int j = 0; j < EPT; j++) {
        if (val[j]) {
            d_qbuf[eidx[j]] = make_float4(acc[j][0], acc[j][1], acc[j][2], acc[j][3]);
#pragma unroll
            for (int w = 0; w < 4; w++) {
                v[w]     += acc[j][w];
                v[4 + w] += acc[j][w] * acc[j][w];
            }
        }
    }

    // block reduction -> d_partial[block][8]
#pragma unroll
    for (int off = 16; off; off >>= 1)
#pragma unroll
        for (int i = 0; i < 8; i++) v[i] += __shfl_xor_sync(0xffffffffu, v[i], off);
    if (lane == 0) {
#pragma unroll
        for (int i = 0; i < 8; i++) red[i][warp] = v[i];
    }
    __syncthreads();
    if (tid < 8) {
        float t = 0.f;
#pragma unroll
        for (int wp = 0; wp < 8; wp++) t += red[tid][wp];
        d_partial[blockIdx.x][tid] = t;
    }
}

// ============================================================
// Kernel 4: fused stats-reduce + normalize (deterministic).
// ============================================================
__global__ void __launch_bounds__(256) normalize_kernel(float* __restrict__ out,
                                                        const float* __restrict__ gamma,
                                                        const float* __restrict__ beta,
                                                        int B, int nparts) {
    __shared__ double sred[256];
    __shared__ float sc_sh[4], sh_sh[4];
    int tid = threadIdx.x;

    {
        int stat = tid & 7, grp = tid >> 3;   // 32 groups
        double acc = 0.0;
        for (int j = grp; j < nparts; j += 32) acc += (double)d_partial[j][stat];
        sred[tid] = acc;
    }
    __syncthreads();
#pragma unroll
    for (int off = 128; off >= 8; off >>= 1) {
        if (tid < off) sred[tid] += sred[tid + off];
        __syncthreads();
    }
    if (tid < 4) {
        double mean = sred[tid] / (double)B;
        double var  = sred[tid + 4] / (double)B - mean * mean;
        double sc = (double)gamma[tid] / sqrt(var + (double)EPS);
        double sh = (double)beta[tid] - mean * sc;
        sc_sh[tid] = (float)sc;
        sh_sh[tid] = (float)sh;
    }
    __syncthreads();

    float4 sc = make_float4(sc_sh[0], sc_sh[1], sc_sh[2], sc_sh[3]);
    float4 sh = make_float4(sh_sh[0], sh_sh[1], sh_sh[2], sh_sh[3]);

    int i = blockIdx.x * blockDim.x + tid;
    if (i < B) {
        float4 q = d_qbuf[i];
        ((float4*)out)[i] = make_float4(fmaf(q.x, sc.x, sh.x),
                                        fmaf(q.y, sc.y, sh.y),
                                        fmaf(q.z, sc.z, sh.z),
                                        fmaf(q.w, sc.w, sh.w));
    }
}

extern "C" void kernel_launch(void* const* d_in, const int* in_sizes, int n_in,
                              void* d_out, int out_size) {
    const float* x       = (const float*)d_in[0];
    const float* weights = (const float*)d_in[1];
    const float* gamma   = (const float*)d_in[2];
    const float* beta    = (const float*)d_in[3];
    int B = in_sizes[0] / 144;
    if (B > BMAX) B = BMAX;

    precompute_kernel<<<NK, 128>>>(weights);

    int pblocks = (B + TILE - 1) / TILE;           // 2048
    pool_kernel<<<pblocks, 256>>>(x, B);

    int NT = EVALBLK * 256;                        // 32768 threads, 4 elems each
    eval_kernel<<<EVALBLK, 256>>>(B, NT);

    int nblocks = (B + 255) / 256;                 // 512
    normalize_kernel<<<nblocks, 256>>>((float*)d_out, gamma, beta, B, EVALBLK);
}